// round 8
// baseline (speedup 1.0000x reference)
#include <cuda_runtime.h>
#include <math.h>

// ---------------------------------------------------------------------------
// DE3 fused: 256-bin histogram entropy, single kernel.
//   out = B * (8 + sum_i p_i log2 p_i),  p_i = counts[i] / (2048*2048)
//
// R7 structure (57.4us, DEPTH=12 pipeline, u16 smem counters) with the
// layout changed to be CONFLICT-FREE: bank == lane for every LDS/STS.
//   counter(warp, lane, bin) at byte
//     warp*16384 + (bin>>1)*128 + lane*4 + (bin&1)*2
//   = bin*64 + (warp*16384 + lane*4) - (bin&1)*62
//   word index = row*32 + lane  ->  bank = lane, always.
// (R7's layout leaked only bin parity into the bank bits -> ~1.5x conflict
//  factor; L1 pipe was 67.5% busy and co-binding with DRAM.)
//
// Grid = 444 x 128 (3 blocks/SM, 64KB smem, one wave).
// Max elements/thread = 1184 < 65535: u16 safe.
// ---------------------------------------------------------------------------

#define NUM_BINS 256
#define THREADS  128
#define BLOCKS   444
#define SMEM_BYTES 65536   // 4 warps * 128 rows * 128 B
#define DEPTH    12

__device__ unsigned int g_counts[NUM_BINS];   // zero-initialized at load
__device__ unsigned int g_done;

__global__ void __launch_bounds__(THREADS, 3)
de3_fused(const float4* __restrict__ in4, int n4,
          const float* __restrict__ in, int n,
          float* __restrict__ out)
{
    extern __shared__ unsigned char smem[];

    // zero private histograms
    {
        uint4* z = reinterpret_cast<uint4*>(smem);
        #pragma unroll
        for (int i = threadIdx.x; i < SMEM_BYTES / 16; i += THREADS)
            z[i] = make_uint4(0u, 0u, 0u, 0u);
    }
    __syncthreads();

    const unsigned lane = threadIdx.x & 31u;
    const unsigned warp = threadIdx.x >> 5;
    const unsigned lanebase = (warp << 14) + (lane << 2);  // warp*16KB + lane*4

    // bump: FMNMX, F2I, AND, IMAD, IMAD, LDS.U16, IADD, STS.U16 — bank==lane
    #define DE3_BUMP(V) do {                                                  \
        unsigned b_ = __float2uint_rz(fminf((V), 255.0f));                    \
        unsigned h_ = b_ & 1u;                                                \
        unsigned short* c_ = reinterpret_cast<unsigned short*>(               \
            smem + (b_ * 64u + lanebase - h_ * 62u));                         \
        *c_ = (unsigned short)(*c_ + 1u);                                     \
    } while (0)
    #define DE3_BUMP4(Q) do { DE3_BUMP((Q).x); DE3_BUMP((Q).y);              \
                              DE3_BUMP((Q).z); DE3_BUMP((Q).w); } while (0)

    const int S  = BLOCKS * THREADS;       // 56832
    const int SD = DEPTH * S;
    int i = blockIdx.x * THREADS + threadIdx.x;

    // ---- DEPTH-deep software pipeline: next batch's LDG.128s issue BEFORE
    //      the current batch's smem work.
    if (i + (DEPTH - 1) * S < n4) {
        float4 buf[DEPTH];
        #pragma unroll
        for (int k = 0; k < DEPTH; ++k) buf[k] = __ldcs(in4 + i + k * S);
        i += SD;
        while (i + (DEPTH - 1) * S < n4) {
            float4 nxt[DEPTH];
            #pragma unroll
            for (int k = 0; k < DEPTH; ++k) nxt[k] = __ldcs(in4 + i + k * S);
            #pragma unroll
            for (int k = 0; k < DEPTH; ++k) DE3_BUMP4(buf[k]);
            #pragma unroll
            for (int k = 0; k < DEPTH; ++k) buf[k] = nxt[k];
            i += SD;
        }
        #pragma unroll
        for (int k = 0; k < DEPTH; ++k) DE3_BUMP4(buf[k]);
    }
    for (; i < n4; i += S) {
        float4 a = __ldcs(in4 + i);
        DE3_BUMP4(a);
    }
    if (blockIdx.x == 0 && (int)threadIdx.x < (n & 3)) {
        float v = in[(n & ~3) + (int)threadIdx.x];
        DE3_BUMP(v);
    }
    #undef DE3_BUMP4
    #undef DE3_BUMP
    __syncthreads();

    // ---- block reduction ---------------------------------------------------
    // Word (warp w, row r, lane l) at word-index w*4096 + r*32 + l holds
    // thread (w,l)'s u16 counters for bins (2r, 2r+1).
    // Thread j = row r = j: sum 32 lanes per warp (packed: 32*1184 < 65536,
    // no carry), unpack per warp. Staggered l: conflict-free.
    const unsigned j = threadIdx.x;
    unsigned tot0 = 0u, tot1 = 0u;   // bins 2j, 2j+1
    {
        const unsigned* w32 = reinterpret_cast<const unsigned*>(smem);
        #pragma unroll
        for (unsigned w = 0; w < 4; ++w) {
            const unsigned rowbase = w * 4096u + j * 32u;
            unsigned acc = 0u;
            #pragma unroll
            for (unsigned k = 0; k < 32; ++k) {
                unsigned l = (k + j) & 31u;
                acc += w32[rowbase + l];
            }
            tot0 += acc & 0xFFFFu;
            tot1 += acc >> 16;
        }
    }
    atomicAdd(&g_counts[2u * j],      tot0);
    atomicAdd(&g_counts[2u * j + 1u], tot1);

    // ---- last-block finalize ----------------------------------------------
    __threadfence();
    __shared__ unsigned ticket;
    if (threadIdx.x == 0) ticket = atomicAdd(&g_done, 1u);
    __syncthreads();

    if (ticket == gridDim.x - 1) {
        const float inv_temp = 1.0f / 4194304.0f;   // 1/(2048*2048)
        unsigned c0 = __ldcg(&g_counts[j]);
        unsigned c1 = __ldcg(&g_counts[j + 128]);
        double term = 0.0;
        if (c0) { float p = (float)c0 * inv_temp; term += (double)(p * log2f(p)); }
        if (c1) { float p = (float)c1 * inv_temp; term += (double)(p * log2f(p)); }

        #pragma unroll
        for (int o = 16; o > 0; o >>= 1)
            term += __shfl_down_sync(0xffffffffu, term, o);

        __shared__ double sred[4];
        if ((j & 31u) == 0u) sred[j >> 5] = term;
        __syncthreads();
        if (j == 0) {
            double s = sred[0] + sred[1] + sred[2] + sred[3];
            float B = (float)(n >> 22);              // n / (2048*2048)
            out[0] = (float)((double)B * (8.0 + s));
        }
        __syncthreads();
        // reset device globals for the next graph replay
        g_counts[j] = 0u;
        g_counts[j + 128] = 0u;
        if (j == 0) g_done = 0u;
    }
}

extern "C" void kernel_launch(void* const* d_in, const int* in_sizes, int n_in,
                              void* d_out, int out_size) {
    const float* img = (const float*)d_in[0];
    int n = in_sizes[0];
    cudaFuncSetAttribute(de3_fused,
                         cudaFuncAttributeMaxDynamicSharedMemorySize, SMEM_BYTES);
    de3_fused<<<BLOCKS, THREADS, SMEM_BYTES>>>(
        (const float4*)img, n >> 2, img, n, (float*)d_out);
}